// round 13
// baseline (speedup 1.0000x reference)
#include <cuda_runtime.h>
#include <cuda_bf16.h>
#include <cstdint>
#include <math.h>

// GMM score via HMMA (mma.sync bf16), symmetry 2-split GEMM, 2 CTAs/SM.
//   G[n,(c,j)] = sum_k A_c[j,k] xh_k        (GEMM on xh only; B in hi+lo splits)
//   x^T A x    = sum_j (xh+2*xl)_j G_j  (+ xl^T A xl dropped, ~2^-18)
//   d[n,c]     = quad + x.(-2 b_c) + k_c   (linear: register-only x = wx - xl, smem b)
//   score      = exp(sum_c w_c log d)

#define ROWB    144           // bytes per smem row (72 bf16, 64 used) — conflict-free ldmatrix
#define XHI_B   18432         // 128 rows * 144
#define HALF_BB 18432
#define CHUNK_B 36864         // hi + lo image of one B chunk

__device__ __align__(16) unsigned char g_B[8][CHUNK_B];
__device__ __align__(16) float g_bm2[1024];   // -2 * b_c[j],  [c*64 + j]
__device__ __align__(8) float g_kc[16];

__device__ __forceinline__ uint32_t smem_u32(const void* p) {
    uint32_t a;
    asm("{ .reg .u64 t; cvta.to.shared.u64 t, %1; cvt.u32.u64 %0, t; }" : "=r"(a) : "l"(p));
    return a;
}
__device__ __forceinline__ uint32_t pk(__nv_bfloat16 a, __nv_bfloat16 b) {
    __nv_bfloat162 t(a, b);
    return *reinterpret_cast<uint32_t*>(&t);
}

#define HMMA(acc, a, b0, b1)                                                  \
    asm volatile("mma.sync.aligned.m16n8k16.row.col.f32.bf16.bf16.f32 "       \
        "{%0,%1,%2,%3},{%4,%5,%6,%7},{%8,%9},{%0,%1,%2,%3};"                  \
        : "+f"((acc)[0]), "+f"((acc)[1]), "+f"((acc)[2]), "+f"((acc)[3])      \
        : "r"((a)[0]), "r"((a)[1]), "r"((a)[2]), "r"((a)[3]), "r"(b0), "r"(b1))

// ---------------- precomp 1: pack B hi/lo + b vectors ----------------
__global__ void precomp1(const float* __restrict__ A, const float* __restrict__ Mn) {
    if (blockIdx.x < 128) {
        const int idx   = blockIdx.x * 256 + threadIdx.x;   // 0..32767
        const int chunk = idx >> 12;
        const int rem   = idx & 4095;
        const int row   = rem >> 5;
        const int kp    = rem & 31;
        const int comp  = chunk * 2 + (row >> 6);
        const int j     = row & 63;
        const float2 v = *(const float2*)(A + comp * 4096 + j * 64 + kp * 2);
        __nv_bfloat16 h0 = __float2bfloat16(v.x), h1 = __float2bfloat16(v.y);
        __nv_bfloat16 l0 = __float2bfloat16(v.x - __bfloat162float(h0));
        __nv_bfloat16 l1 = __float2bfloat16(v.y - __bfloat162float(h1));
        *(uint32_t*)(g_B[chunk] + row * ROWB + kp * 4)           = pk(h0, h1);
        *(uint32_t*)(g_B[chunk] + HALF_BB + row * ROWB + kp * 4) = pk(l0, l1);
    } else {
        // b_c[j] = A_c[j,:] . m_c
        const int bi = (blockIdx.x - 128) * 256 + threadIdx.x;  // 0..1023
        const int c = bi >> 6, j = bi & 63;
        const float4* Ar = (const float4*)(A + c * 4096 + j * 64);
        const float4* mr = (const float4*)(Mn + c * 64);
        float s0 = 0, s1 = 0, s2 = 0, s3 = 0;
        #pragma unroll
        for (int t = 0; t < 16; t++) {
            float4 a = Ar[t], m = mr[t];
            s0 = fmaf(a.x, m.x, s0); s1 = fmaf(a.y, m.y, s1);
            s2 = fmaf(a.z, m.z, s2); s3 = fmaf(a.w, m.w, s3);
        }
        g_bm2[bi] = -2.0f * ((s0 + s1) + (s2 + s3));
    }
}

// ---------------- precomp 2: k_c = m_c^T b_c ----------------
__global__ void precomp2(const float* __restrict__ Mn) {
    const int c = threadIdx.x;
    if (c < 16) {
        float acc = 0.0f;
        #pragma unroll
        for (int j = 0; j < 64; j++)
            acc = fmaf(Mn[c * 64 + j], -0.5f * g_bm2[c * 64 + j], acc);
        g_kc[c] = acc;
    }
}

// ---------------- main kernel ----------------
// smem: Xhi [0,18432) | 2 x B buf | w 64B | kc 64B | bm2 4KB
#define SM_B0  XHI_B                          // 18432
#define SM_W   (XHI_B + 2 * CHUNK_B)          // 92160
#define SM_KC  (SM_W + 64)                    // 92224
#define SM_BM  (SM_KC + 64)                   // 92288
#define SMEM_BYTES (SM_BM + 4096)             // 96384

__global__ void __launch_bounds__(256, 2)
gmm_hmma_kernel(const float* __restrict__ X, const float* __restrict__ W,
                float* __restrict__ out, int N)
{
    extern __shared__ unsigned char smem[];
    const uint32_t sb = smem_u32(smem);
    const int tid  = threadIdx.x;
    const int wid  = tid >> 5;
    const int lane = tid & 31;
    const int base = blockIdx.x * 128;

    // prefetch B chunk 0
    {
        size_t gsrc = __cvta_generic_to_global(g_B[0]);
        const uint32_t dst = sb + SM_B0;
        #pragma unroll
        for (int i = 0; i < 9; i++) {
            int o = (i * 256 + tid) * 16;
            asm volatile("cp.async.cg.shared.global [%0], [%1], 16;"
                         :: "r"(dst + o), "l"(gsrc + o));
        }
        asm volatile("cp.async.commit_group;");
    }
    if (tid < 16) {
        *(float*)(smem + SM_W  + 4 * tid) = W[tid];
        *(float*)(smem + SM_KC + 4 * tid) = g_kc[tid];
    }
    ((float4*)(smem + SM_BM))[tid] = ((const float4*)g_bm2)[tid];  // 4KB bm2 -> smem

    // stage Xhi: row = tid>>1, half = tid&1 covers 32 cols
    {
        const int row = tid >> 1, half = tid & 1;
        const float4* xg = (const float4*)(X + (size_t)(base + row) * 64 + half * 32);
        unsigned char* rp = smem + row * ROWB + half * 64;
        #pragma unroll
        for (int q = 0; q < 8; q++) {
            float4 v = xg[q];
            *(uint2*)(rp + q * 8) = make_uint2(
                pk(__float2bfloat16(v.x), __float2bfloat16(v.y)),
                pk(__float2bfloat16(v.z), __float2bfloat16(v.w)));
        }
    }

    const int r0g = wid * 16 + (lane >> 2);   // this thread's quad row (0..127 in CTA)
    const int jb  = 2 * (lane & 3);           // quad j-offset

    // quad weights wx = xh + 2*xl (fp32) and xl packed bf16 (exact) for x = wx - xl
    float    wx[2][16];
    uint32_t xlp[2][8];
    {
        #pragma unroll
        for (int rh = 0; rh < 2; rh++) {
            const float* xr = X + (size_t)(base + r0g + rh * 8) * 64 + jb;
            #pragma unroll
            for (int q = 0; q < 8; q++) {
                float2 v = *(const float2*)(xr + q * 8);
                __nv_bfloat16 h0 = __float2bfloat16(v.x), h1 = __float2bfloat16(v.y);
                float l0 = v.x - __bfloat162float(h0);
                float l1 = v.y - __bfloat162float(h1);
                wx[rh][2*q]   = __bfloat162float(h0) + 2.0f * l0;
                wx[rh][2*q+1] = __bfloat162float(h1) + 2.0f * l1;
                xlp[rh][q] = pk(__float2bfloat16(l0), __float2bfloat16(l1));
            }
        }
    }
    __syncthreads();

    // A-fragments (Xhi only)
    uint32_t Ahi[4][4];
    {
        const int arow = wid * 16 + ((lane >> 3) & 1) * 8 + (lane & 7);
        const uint32_t coff = (lane >> 4) * 16;
        #pragma unroll
        for (int s = 0; s < 4; s++) {
            uint32_t ah = sb + arow * ROWB + coff + s * 32;
            asm volatile("ldmatrix.sync.aligned.m8n8.x4.shared.b16 {%0,%1,%2,%3}, [%4];"
                : "=r"(Ahi[s][0]), "=r"(Ahi[s][1]), "=r"(Ahi[s][2]), "=r"(Ahi[s][3]) : "r"(ah));
        }
    }

    float la0 = 0.0f, la1 = 0.0f;

    for (int c = 0; c < 8; c++) {
        asm volatile("cp.async.wait_group 0;");
        __syncthreads();

        if (c + 1 < 8) {
            size_t gsrc = __cvta_generic_to_global(g_B[c + 1]);
            const uint32_t dst = sb + SM_B0 + ((c + 1) & 1) * CHUNK_B;
            #pragma unroll
            for (int i = 0; i < 9; i++) {
                int o = (i * 256 + tid) * 16;
                asm volatile("cp.async.cg.shared.global [%0], [%1], 16;"
                             :: "r"(dst + o), "l"(gsrc + o));
            }
            asm volatile("cp.async.commit_group;");
        }

        // exact linear term, register-only x: lp[rh][half] = quad-partial x.(-2 b_cc)
        float lp00 = 0.f, lp01 = 0.f, lp10 = 0.f, lp11 = 0.f;
        {
            #pragma unroll
            for (int q = 0; q < 8; q++) {
                float2 b0 = *(const float2*)(smem + SM_BM + ((2*c) * 64 + q * 8 + jb) * 4);
                float2 b1 = *(const float2*)(smem + SM_BM + ((2*c + 1) * 64 + q * 8 + jb) * 4);
                __nv_bfloat162 l0p = *reinterpret_cast<__nv_bfloat162*>(&xlp[0][q]);
                __nv_bfloat162 l1p = *reinterpret_cast<__nv_bfloat162*>(&xlp[1][q]);
                const float x00 = wx[0][2*q]   - __bfloat162float(l0p.x);
                const float x01 = wx[0][2*q+1] - __bfloat162float(l0p.y);
                const float x10 = wx[1][2*q]   - __bfloat162float(l1p.x);
                const float x11 = wx[1][2*q+1] - __bfloat162float(l1p.y);
                lp00 = fmaf(x00, b0.x, fmaf(x01, b0.y, lp00));
                lp01 = fmaf(x00, b1.x, fmaf(x01, b1.y, lp01));
                lp10 = fmaf(x10, b0.x, fmaf(x11, b0.y, lp10));
                lp11 = fmaf(x10, b1.x, fmaf(x11, b1.y, lp11));
            }
        }
        const float2 kc = *(const float2*)(smem + SM_KC + 8 * c);

        const uint32_t Bb = sb + SM_B0 + (c & 1) * CHUNK_B
                          + ((lane >> 4) * 8 + (lane & 7)) * ROWB + ((lane >> 3) & 1) * 16;

        #pragma unroll
        for (int half = 0; half < 2; half++) {
            const int cc = 2 * c + half;
            float acc[8][4];
            #pragma unroll
            for (int t = 0; t < 8; t++) { acc[t][0]=0.f; acc[t][1]=0.f; acc[t][2]=0.f; acc[t][3]=0.f; }

            #pragma unroll
            for (int t2 = 0; t2 < 4; t2++) {
                #pragma unroll
                for (int s = 0; s < 4; s++) {
                    uint32_t bh0, bh1, bh2, bh3, bl0, bl1, bl2, bl3;
                    const uint32_t ab = Bb + (half * 64 + t2 * 16) * ROWB + s * 32;
                    asm volatile("ldmatrix.sync.aligned.m8n8.x4.shared.b16 {%0,%1,%2,%3}, [%4];"
                                 : "=r"(bh0), "=r"(bh1), "=r"(bh2), "=r"(bh3) : "r"(ab));
                    asm volatile("ldmatrix.sync.aligned.m8n8.x4.shared.b16 {%0,%1,%2,%3}, [%4];"
                                 : "=r"(bl0), "=r"(bl1), "=r"(bl2), "=r"(bl3) : "r"(ab + HALF_BB));
                    HMMA(acc[2*t2],   Ahi[s], bh0, bh1);
                    HMMA(acc[2*t2+1], Ahi[s], bh2, bh3);
                    HMMA(acc[2*t2],   Ahi[s], bl0, bl1);
                    HMMA(acc[2*t2+1], Ahi[s], bl2, bl3);
                }
            }

            // epilogue: p seeded with quad-partial linear; shfl reduces quad+linear together
            float p0 = half ? lp01 : lp00;
            float p1 = half ? lp11 : lp10;
            #pragma unroll
            for (int t = 0; t < 8; t++) {
                p0 = fmaf(wx[0][t*2],   acc[t][0], p0);
                p0 = fmaf(wx[0][t*2+1], acc[t][1], p0);
                p1 = fmaf(wx[1][t*2],   acc[t][2], p1);
                p1 = fmaf(wx[1][t*2+1], acc[t][3], p1);
            }
            p0 += __shfl_xor_sync(0xFFFFFFFFu, p0, 1); p0 += __shfl_xor_sync(0xFFFFFFFFu, p0, 2);
            p1 += __shfl_xor_sync(0xFFFFFFFFu, p1, 1); p1 += __shfl_xor_sync(0xFFFFFFFFu, p1, 2);

            const float wc = *(float*)(smem + SM_W + 4 * cc);
            const float kk = half ? kc.y : kc.x;
            la0 = fmaf(wc, __logf(p0 + kk), la0);
            la1 = fmaf(wc, __logf(p1 + kk), la1);
        }
    }

    if ((lane & 3) == 0) {
        out[base + r0g]     = __expf(la0);
        out[base + r0g + 8] = __expf(la1);
    }
}

// ---------------- launch ----------------
extern "C" void kernel_launch(void* const* d_in, const int* in_sizes, int n_in,
                              void* d_out, int out_size)
{
    const float* X     = (const float*)d_in[0];   // [N, 64]
    const float* Ainv  = (const float*)d_in[1];   // [16, 64, 64]
    const float* Means = (const float*)d_in[2];   // [16, 64]
    const float* W     = (const float*)d_in[3];   // [16]
    float* out = (float*)d_out;

    const int N = in_sizes[0] / 64;

    cudaFuncSetAttribute(gmm_hmma_kernel, cudaFuncAttributeMaxDynamicSharedMemorySize, SMEM_BYTES);

    precomp1<<<132, 256>>>(Ainv, Means);
    precomp2<<<1, 32>>>(Means);
    gmm_hmma_kernel<<<N / 128, 256, SMEM_BYTES>>>(X, W, out, N);
}

// round 14
// speedup vs baseline: 1.0841x; 1.0841x over previous
#include <cuda_runtime.h>
#include <cuda_bf16.h>
#include <cstdint>
#include <math.h>

// GMM score via HMMA (mma.sync bf16), symmetry 2-split GEMM, 2 CTAs/SM.
//   G[n,(c,j)] = sum_k A_c[j,k] xh_k        (GEMM on xh only; B in hi+lo splits)
//   x^T A x    = sum_j (xh+2*xl)_j G_j  (+ xl^T A xl dropped, ~2^-18)
//   d[n,c]     = quad + sum_j (xh+xl)_j * (-2 b_c[j]) + k_c
//   score      = exp(sum_c w_c log d)
// CTA: 128 samples, 8 warps; chunk = 2 comps processed as two sequential halves
// (acc[8][4] reused) to fit 128 regs -> 2 CTAs/SM.

#define ROWB    144           // bytes per smem row (72 bf16, 64 used) — conflict-free ldmatrix
#define XHI_B   18432         // 128 rows * 144
#define HALF_BB 18432
#define CHUNK_B 36864         // hi + lo image of one B chunk

__device__ __align__(16) unsigned char g_B[8][CHUNK_B];
__device__ __align__(16) float g_bm2[1024];   // -2 * b_c[j],  [c*64 + j]
__device__ float g_kc[16];

__device__ __forceinline__ uint32_t smem_u32(const void* p) {
    uint32_t a;
    asm("{ .reg .u64 t; cvta.to.shared.u64 t, %1; cvt.u32.u64 %0, t; }" : "=r"(a) : "l"(p));
    return a;
}
__device__ __forceinline__ uint32_t pk(__nv_bfloat16 a, __nv_bfloat16 b) {
    __nv_bfloat162 t(a, b);
    return *reinterpret_cast<uint32_t*>(&t);
}

#define HMMA(acc, a, b0, b1)                                                  \
    asm volatile("mma.sync.aligned.m16n8k16.row.col.f32.bf16.bf16.f32 "       \
        "{%0,%1,%2,%3},{%4,%5,%6,%7},{%8,%9},{%0,%1,%2,%3};"                  \
        : "+f"((acc)[0]), "+f"((acc)[1]), "+f"((acc)[2]), "+f"((acc)[3])      \
        : "r"((a)[0]), "r"((a)[1]), "r"((a)[2]), "r"((a)[3]), "r"(b0), "r"(b1))

// ---------------- precomp 1: pack B hi/lo + b vectors ----------------
__global__ void precomp1(const float* __restrict__ A, const float* __restrict__ Mn) {
    if (blockIdx.x < 128) {
        const int idx   = blockIdx.x * 256 + threadIdx.x;   // 0..32767
        const int chunk = idx >> 12;
        const int rem   = idx & 4095;
        const int row   = rem >> 5;     // chunk-local col (par*64 + j)
        const int kp    = rem & 31;
        const int comp  = chunk * 2 + (row >> 6);
        const int j     = row & 63;
        const float2 v = *(const float2*)(A + comp * 4096 + j * 64 + kp * 2);
        __nv_bfloat16 h0 = __float2bfloat16(v.x), h1 = __float2bfloat16(v.y);
        __nv_bfloat16 l0 = __float2bfloat16(v.x - __bfloat162float(h0));
        __nv_bfloat16 l1 = __float2bfloat16(v.y - __bfloat162float(h1));
        *(uint32_t*)(g_B[chunk] + row * ROWB + kp * 4)           = pk(h0, h1);
        *(uint32_t*)(g_B[chunk] + HALF_BB + row * ROWB + kp * 4) = pk(l0, l1);
    } else {
        // b_c[j] = A_c[j,:] . m_c
        const int bi = (blockIdx.x - 128) * 256 + threadIdx.x;  // 0..1023
        const int c = bi >> 6, j = bi & 63;
        const float4* Ar = (const float4*)(A + c * 4096 + j * 64);
        const float4* mr = (const float4*)(Mn + c * 64);
        float s0 = 0, s1 = 0, s2 = 0, s3 = 0;
        #pragma unroll
        for (int t = 0; t < 16; t++) {
            float4 a = Ar[t], m = mr[t];
            s0 = fmaf(a.x, m.x, s0); s1 = fmaf(a.y, m.y, s1);
            s2 = fmaf(a.z, m.z, s2); s3 = fmaf(a.w, m.w, s3);
        }
        g_bm2[bi] = -2.0f * ((s0 + s1) + (s2 + s3));
    }
}

// ---------------- precomp 2: k_c = m_c^T b_c ----------------
__global__ void precomp2(const float* __restrict__ Mn) {
    const int c = threadIdx.x;
    if (c < 16) {
        float acc = 0.0f;
        #pragma unroll
        for (int j = 0; j < 64; j++)
            acc = fmaf(Mn[c * 64 + j], -0.5f * g_bm2[c * 64 + j], acc);
        g_kc[c] = acc;
    }
}

// ---------------- main kernel ----------------
// smem: Xhi [0,18432) | 2 x B buf (36864 each) | bm2 4KB | w/kc 128B
#define SM_B0  XHI_B                          // 18432
#define SM_BM  (XHI_B + 2 * CHUNK_B)          // 92160
#define SM_WKC (SM_BM + 4096)                 // 96256
#define SMEM_BYTES (SM_WKC + 128)             // 96384

__global__ void __launch_bounds__(256, 2)
gmm_hmma_kernel(const float* __restrict__ X, const float* __restrict__ W,
                float* __restrict__ out, int N)
{
    extern __shared__ unsigned char smem[];
    const uint32_t sb = smem_u32(smem);
    const int tid  = threadIdx.x;
    const int wid  = tid >> 5;
    const int lane = tid & 31;
    const int base = blockIdx.x * 128;

    // prefetch B chunk 0
    {
        size_t gsrc = __cvta_generic_to_global(g_B[0]);
        const uint32_t dst = sb + SM_B0;
        #pragma unroll
        for (int i = 0; i < 9; i++) {                 // 9*256*16 = 36864
            int o = (i * 256 + tid) * 16;
            asm volatile("cp.async.cg.shared.global [%0], [%1], 16;"
                         :: "r"(dst + o), "l"(gsrc + o));
        }
        asm volatile("cp.async.commit_group;");
    }
    if (tid < 16) {
        *(float*)(smem + SM_WKC + 4 * tid)      = W[tid];
        *(float*)(smem + SM_WKC + 64 + 4 * tid) = g_kc[tid];
    }
    ((float4*)(smem + SM_BM))[tid] = ((const float4*)g_bm2)[tid];  // 4KB

    // stage Xhi only: row = tid>>1, half = tid&1 covers 32 cols
    {
        const int row = tid >> 1, half = tid & 1;
        const float4* xg = (const float4*)(X + (size_t)(base + row) * 64 + half * 32);
        unsigned char* rp = smem + row * ROWB + half * 64;
        #pragma unroll
        for (int q = 0; q < 8; q++) {
            float4 v = xg[q];
            *(uint2*)(rp + q * 8) = make_uint2(
                pk(__float2bfloat16(v.x), __float2bfloat16(v.y)),
                pk(__float2bfloat16(v.z), __float2bfloat16(v.w)));
        }
    }

    // epilogue weights straight from global X (no Xlo smem image):
    //   wx  = xh + 2*xl (fp32), xlp = xl packed bf16 (exact) -> wxe = wx - xl
    float    wx[2][16];
    uint32_t xlp[2][8];
    {
        const int r0 = wid * 16 + (lane >> 2);
        #pragma unroll
        for (int rh = 0; rh < 2; rh++) {
            const float* xr = X + (size_t)(base + r0 + rh * 8) * 64 + 2 * (lane & 3);
            #pragma unroll
            for (int q = 0; q < 8; q++) {
                float2 v = *(const float2*)(xr + q * 8);
                __nv_bfloat16 h0 = __float2bfloat16(v.x), h1 = __float2bfloat16(v.y);
                float l0 = v.x - __bfloat162float(h0);
                float l1 = v.y - __bfloat162float(h1);
                wx[rh][2*q]   = __bfloat162float(h0) + 2.0f * l0;
                wx[rh][2*q+1] = __bfloat162float(h1) + 2.0f * l1;
                xlp[rh][q] = pk(__float2bfloat16(l0), __float2bfloat16(l1));
            }
        }
    }
    __syncthreads();

    // A-fragments (Xhi only)
    uint32_t Ahi[4][4];
    {
        const int arow = wid * 16 + ((lane >> 3) & 1) * 8 + (lane & 7);
        const uint32_t coff = (lane >> 4) * 16;
        #pragma unroll
        for (int s = 0; s < 4; s++) {
            uint32_t ah = sb + arow * ROWB + coff + s * 32;
            asm volatile("ldmatrix.sync.aligned.m8n8.x4.shared.b16 {%0,%1,%2,%3}, [%4];"
                : "=r"(Ahi[s][0]), "=r"(Ahi[s][1]), "=r"(Ahi[s][2]), "=r"(Ahi[s][3]) : "r"(ah));
        }
    }

    float la0 = 0.0f, la1 = 0.0f;

    for (int c = 0; c < 8; c++) {
        asm volatile("cp.async.wait_group 0;");  // chunk c resident
        __syncthreads();                          // visible to all; buf (c+1)&1 free

        if (c + 1 < 8) {
            size_t gsrc = __cvta_generic_to_global(g_B[c + 1]);
            const uint32_t dst = sb + SM_B0 + ((c + 1) & 1) * CHUNK_B;
            #pragma unroll
            for (int i = 0; i < 9; i++) {
                int o = (i * 256 + tid) * 16;
                asm volatile("cp.async.cg.shared.global [%0], [%1], 16;"
                             :: "r"(dst + o), "l"(gsrc + o));
            }
            asm volatile("cp.async.commit_group;");
        }

        const uint32_t Bb = sb + SM_B0 + (c & 1) * CHUNK_B
                          + ((lane >> 4) * 8 + (lane & 7)) * ROWB + ((lane >> 3) & 1) * 16;

        #pragma unroll
        for (int half = 0; half < 2; half++) {
            const int cc = 2 * c + half;
            float acc[8][4];
            #pragma unroll
            for (int t = 0; t < 8; t++) { acc[t][0]=0.f; acc[t][1]=0.f; acc[t][2]=0.f; acc[t][3]=0.f; }

            #pragma unroll
            for (int t2 = 0; t2 < 4; t2++) {
                #pragma unroll
                for (int s = 0; s < 4; s++) {
                    uint32_t bh0, bh1, bh2, bh3, bl0, bl1, bl2, bl3;
                    const uint32_t ab = Bb + (half * 64 + t2 * 16) * ROWB + s * 32;
                    asm volatile("ldmatrix.sync.aligned.m8n8.x4.shared.b16 {%0,%1,%2,%3}, [%4];"
                                 : "=r"(bh0), "=r"(bh1), "=r"(bh2), "=r"(bh3) : "r"(ab));
                    asm volatile("ldmatrix.sync.aligned.m8n8.x4.shared.b16 {%0,%1,%2,%3}, [%4];"
                                 : "=r"(bl0), "=r"(bl1), "=r"(bl2), "=r"(bl3) : "r"(ab + HALF_BB));
                    HMMA(acc[2*t2],   Ahi[s], bh0, bh1);
                    HMMA(acc[2*t2+1], Ahi[s], bh2, bh3);
                    HMMA(acc[2*t2],   Ahi[s], bl0, bl1);
                    HMMA(acc[2*t2+1], Ahi[s], bl2, bl3);
                }
            }

            // epilogue for component cc: quad (wx . G) + linear (wxe . -2b)
            const float* bm = (const float*)(smem + SM_BM) + cc * 64;
            float p0 = 0.f, p1 = 0.f;
            #pragma unroll
            for (int i = 0; i < 16; i++) {
                const int j = (i >> 1) * 8 + 2 * (lane & 3) + (i & 1);
                const float b = bm[j];
                __nv_bfloat162 lp0 = *reinterpret_cast<__nv_bfloat162*>(&xlp[0][i >> 1]);
                __nv_bfloat162 lp1 = *reinterpret_cast<__nv_bfloat162*>(&xlp[1][i >> 1]);
                const float l0 = __bfloat162float((i & 1) ? lp0.y : lp0.x);
                const float l1 = __bfloat162float((i & 1) ? lp1.y : lp1.x);
                p0 = fmaf(wx[0][i] - l0, b, p0);
                p1 = fmaf(wx[1][i] - l1, b, p1);
            }
            #pragma unroll
            for (int t = 0; t < 8; t++) {
                p0 = fmaf(wx[0][t*2],   acc[t][0], p0);
                p0 = fmaf(wx[0][t*2+1], acc[t][1], p0);
                p1 = fmaf(wx[1][t*2],   acc[t][2], p1);
                p1 = fmaf(wx[1][t*2+1], acc[t][3], p1);
            }
            p0 += __shfl_xor_sync(0xFFFFFFFFu, p0, 1); p0 += __shfl_xor_sync(0xFFFFFFFFu, p0, 2);
            p1 += __shfl_xor_sync(0xFFFFFFFFu, p1, 1); p1 += __shfl_xor_sync(0xFFFFFFFFu, p1, 2);

            const float wc = *(float*)(smem + SM_WKC + 4 * cc);
            const float kc = *(float*)(smem + SM_WKC + 64 + 4 * cc);
            la0 = fmaf(wc, __logf(p0 + kc), la0);
            la1 = fmaf(wc, __logf(p1 + kc), la1);
        }
    }

    if ((lane & 3) == 0) {
        const int r0 = wid * 16 + (lane >> 2);
        out[base + r0]     = __expf(la0);
        out[base + r0 + 8] = __expf(la1);
    }
}

// ---------------- launch ----------------
extern "C" void kernel_launch(void* const* d_in, const int* in_sizes, int n_in,
                              void* d_out, int out_size)
{
    const float* X     = (const float*)d_in[0];   // [N, 64]
    const float* Ainv  = (const float*)d_in[1];   // [16, 64, 64]
    const float* Means = (const float*)d_in[2];   // [16, 64]
    const float* W     = (const float*)d_in[3];   // [16]
    float* out = (float*)d_out;

    const int N = in_sizes[0] / 64;

    cudaFuncSetAttribute(gmm_hmma_kernel, cudaFuncAttributeMaxDynamicSharedMemorySize, SMEM_BYTES);

    precomp1<<<132, 256>>>(Ainv, Means);
    precomp2<<<1, 32>>>(Means);
    gmm_hmma_kernel<<<N / 128, 256, SMEM_BYTES>>>(X, W, out, N);
}